// round 13
// baseline (speedup 1.0000x reference)
#include <cuda_runtime.h>
#include <cstdint>

// Problem shape (fixed by reference setup_inputs)
#define BATCH 8
#define MPRED 100
#define NGT   32
#define HWPIX 65536   // 256*256
#define F4_PER_BN (HWPIX / 4)                  // 16384 float4 per (b,n)
#define GXBLK 4                                 // CTAs per (b,n)
#define F4_PER_BLK (F4_PER_BN / GXBLK)          // 4096 float4 per CTA
#define F4_PER_WARP (F4_PER_BLK / 8)            // 512 float4 per warp
#define F4_PER_LANE (F4_PER_WARP / 32)          // 16 float4 per lane
#define NCHUNK_W 8                              // chunks per spec warp
#define IT_PER_CHUNK (F4_PER_LANE / NCHUNK_W)   // 2 float4 per chunk

// ---------------------------------------------------------------------------
// Uniform grid: 1024 CTAs, 256 threads. In each CTA:
//   warp 0   : redundantly computes the greedy match for this CTA's batch
//              (lane = GT; entirely warp-local, ~2-3us, hidden under stores),
//              publishes to SHARED memory, then does its gather share in
//              known mode. xq==0 CTA also writes the tail scalars.
//   warps 1-7: speculatively zero-fill their shares, polling the shared flag
//              (LDS, ~29cy, warp-autonomous, no barriers) between chunks;
//              redo zeroed chunks if the row turns out matched.
// No cross-CTA communication at all: no sentinels, no atomics, no replay
// state, no deadlock/occupancy coupling.
// ---------------------------------------------------------------------------
__global__ void __launch_bounds__(256, 7) fused_kernel(
                             const float* __restrict__ pred_boxes,  // [B,M,4]
                             const float* __restrict__ gt_boxes,    // [B,N,4]
                             const float* __restrict__ pred_scores, // [B,M]
                             const float* __restrict__ pred_masks,  // [B,M,H,W]
                             const float* __restrict__ mask_score,  // [B,M]
                             float* __restrict__ out)
{
    const int u    = blockIdx.x;          // 0..1023
    const int bn   = u >> 2;              // (b,n) id
    const int b    = bn >> 5;
    const int n    = bn & 31;
    const int xq   = u & 3;               // quarter index
    const int tid  = threadIdx.x;
    const int wid  = tid >> 5;
    const int lane = tid & 31;

    __shared__ float4 s_pbox[MPRED];
    __shared__ float  s_score[MPRED];
    __shared__ float  s_iou[MPRED * NGT];
    __shared__ int    s_hits[MPRED];
    __shared__ int    s_sorted[MPRED];
    __shared__ int    s_gtm[NGT];
    __shared__ int    s_flag;             // 0 = match pending, 1 = done

    if (tid == 0) s_flag = 0;
    __syncthreads();                      // only block barrier in the kernel

    // per-thread gather geometry: warp-contiguous 8 KB share
    const int base = xq * F4_PER_BLK + wid * F4_PER_WARP + lane;
    float4* o = reinterpret_cast<float4*>(out) + (long long)bn * F4_PER_BN + base;
    const float4 z = make_float4(0.0f, 0.0f, 0.0f, 0.0f);
    volatile int* vflag = (volatile int*)&s_flag;
    volatile int* vgtm  = (volatile int*)s_gtm;

    if (wid == 0) {
        // ================= WARP 0: REDUNDANT MATCH (lane = GT) =================
        const float4* pb4 = reinterpret_cast<const float4*>(pred_boxes + b * MPRED * 4);
        const float*  ps  = pred_scores + b * MPRED;
        for (int i = lane; i < MPRED; i += 32) {
            s_pbox[i]  = pb4[i];
            s_score[i] = ps[i];
        }
        __syncwarp();

        const float* gb = gt_boxes + (b * NGT + lane) * 4;
        const float g0 = gb[0], g1 = gb[1], g2 = gb[2], g3 = gb[3];
        const float area2 = (g2 - g0) * (g3 - g1);

        // Phase A: IoU column for this lane's GT; hit bits accumulated in
        // registers (NO per-iteration ballot -> fully pipelined).
        unsigned hitm[4] = {0u, 0u, 0u, 0u};
        #pragma unroll 4
        for (int p = 0; p < MPRED; p++) {
            const float4 pbx = s_pbox[p];           // broadcast LDS
            const float area1 = (pbx.z - pbx.x) * (pbx.w - pbx.y);
            const float lx = fmaxf(pbx.x, g0), ly = fmaxf(pbx.y, g1);
            const float rx = fminf(pbx.z, g2), ry = fminf(pbx.w, g3);
            const float w  = fmaxf(rx - lx, 0.0f);
            const float h  = fmaxf(ry - ly, 0.0f);
            const float inter = w * h;
            const float iou = __fdividef(inter, area1 + area2 - inter);
            s_iou[p * NGT + lane] = iou;
            if (iou >= 0.5f) hitm[p >> 5] |= (1u << (p & 31));
        }
        __syncwarp();

        // Compaction: OR hit bits across lanes, then 4 ballots
        int nh = 0;
        #pragma unroll
        for (int k = 0; k < 4; k++) {
            const unsigned word = __reduce_or_sync(0xffffffffu, hitm[k]);
            const int p = k * 32 + lane;
            const bool f = (p < MPRED) && ((word >> lane) & 1u) && (s_score[p] >= 0.0f);
            const unsigned bal = __ballot_sync(0xffffffffu, f);
            if (f) s_hits[nh + __popc(bal & ((1u << lane) - 1u))] = p;
            nh += __popc(bal);
        }
        const int K = nh;

        // Stable descending rank-sort of hit preds (== jnp.argsort(-scores))
        for (int t = lane; t < K; t += 32) {
            const int   hi = s_hits[t];
            const float si = s_score[hi];
            int rank = 0;
            for (int v = 0; v < K; v++) {
                const int   hv = s_hits[v];
                const float sv = s_score[hv];
                rank += (sv > si) || (sv == si && hv < hi);
            }
            s_sorted[rank] = hi;
        }
        __syncwarp();

        // Serial greedy scan
        int   gtm  = -1;
        float biou = 0.0f;
        for (int t = 0; t < K; t++) {
            const int   i   = s_sorted[t];
            const float iou = s_iou[i * NGT + lane];
            // Faithful to reference: gt available iff gtm <= 0 (intentional "bug")
            const bool  valid = (gtm <= 0) && (iou >= 0.5f);
            const unsigned key  = valid ? __float_as_uint(iou) : 0u;
            const unsigned kmax = __reduce_max_sync(0xffffffffu, key);
            if (kmax != 0u) {
                const unsigned bal = __ballot_sync(0xffffffffu, key == kmax);
                const int m = __ffs(bal) - 1;   // lowest lane = jnp.argmax
                if (lane == m) { gtm = i; biou = iou; }
            }
        }

        // Publish to shared: gtm array, fence, flag
        vgtm[lane] = gtm;
        __threadfence_block();
        if (lane == 0) *vflag = 1;

        // Tail scalars: only the xq==0 CTA, lane == n
        if (xq == 0 && lane == n) {
            float* flags_out = out + (long long)BATCH * NGT * HWPIX;
            float* gtm_out   = flags_out + BATCH * NGT;
            float* biou_out  = gtm_out   + BATCH * NGT;
            flags_out[bn] = (gtm > -1) ? mask_score[b * MPRED + gtm] : 0.0f;
            gtm_out[bn]   = (float)gtm;
            biou_out[bn]  = biou;
        }

        // Warp 0's own gather share, known mode
        const int g = __shfl_sync(0xffffffffu, gtm, n);
        if (g > -1) {
            const float4* src = reinterpret_cast<const float4*>(pred_masks)
                              + (long long)(b * MPRED + g) * F4_PER_BN + base;
            #pragma unroll 4
            for (int k = 0; k < F4_PER_LANE; k++)
                o[k * 32] = src[k * 32];
        } else {
            #pragma unroll 4
            for (int k = 0; k < F4_PER_LANE; k++)
                o[k * 32] = z;
        }
    } else {
        // ============ WARPS 1-7: SPECULATIVE ZERO + LDS POLL ============
        int g = -2;          // -2 = unknown
        int zeroed = 0;      // chunks written speculatively as zero

        #pragma unroll
        for (int c = 0; c < NCHUNK_W; c++) {
            if (g == -2 && *vflag) g = vgtm[n];   // LDS broadcast, ~29cy
            if (g >= 0) {
                const float4* src = reinterpret_cast<const float4*>(pred_masks)
                                  + (long long)(b * MPRED + g) * F4_PER_BN + base;
                #pragma unroll
                for (int k = 0; k < IT_PER_CHUNK; k++)
                    o[(c * IT_PER_CHUNK + k) * 32] = src[(c * IT_PER_CHUNK + k) * 32];
            } else {
                #pragma unroll
                for (int k = 0; k < IT_PER_CHUNK; k++)
                    o[(c * IT_PER_CHUNK + k) * 32] = z;
                if (g == -2) zeroed = c + 1;
            }
        }

        // Still unknown: spin on the shared flag (cheap, SM-local)
        if (g == -2) {
            while (!*vflag) { __nanosleep(32); }
            g = vgtm[n];
        }

        // Matched: redo speculatively-zeroed chunks with real data.
        if (g > -1) {
            const float4* src = reinterpret_cast<const float4*>(pred_masks)
                              + (long long)(b * MPRED + g) * F4_PER_BN + base;
            for (int c = 0; c < zeroed; c++) {
                #pragma unroll
                for (int k = 0; k < IT_PER_CHUNK; k++)
                    o[(c * IT_PER_CHUNK + k) * 32] = src[(c * IT_PER_CHUNK + k) * 32];
            }
        }
    }
}

// ---------------------------------------------------------------------------
extern "C" void kernel_launch(void* const* d_in, const int* in_sizes, int n_in,
                              void* d_out, int out_size)
{
    const float* pred_boxes  = (const float*)d_in[0];
    const float* gt_boxes    = (const float*)d_in[1];
    const float* pred_scores = (const float*)d_in[2];
    const float* pred_masks  = (const float*)d_in[3];
    const float* mask_score  = (const float*)d_in[4];
    float* out = (float*)d_out;

    fused_kernel<<<BATCH * NGT * GXBLK, 256>>>(pred_boxes, gt_boxes, pred_scores,
                                               pred_masks, mask_score, out);
}

// round 14
// speedup vs baseline: 1.6355x; 1.6355x over previous
#include <cuda_runtime.h>
#include <cstdint>

// Problem shape (fixed by reference setup_inputs)
#define BATCH 8
#define MPRED 100
#define NGT   32
#define HWPIX 65536   // 256*256
#define F4_PER_BN (HWPIX / 4)                  // 16384 float4 per (b,n)
#define GXBLK 8                                 // gather CTAs per (b,n)
#define F4_PER_BLK (F4_PER_BN / GXBLK)          // 2048
#define F4_PER_THR (F4_PER_BLK / 256)           // 8 float4 per thread
#define NCHUNK 4                                // speculation chunks
#define IT_PER_CHUNK (F4_PER_THR / NCHUNK)      // 2 float4 per chunk (8 KB/CTA)
#define NMATCH BATCH

// Cross-CTA sync: sentinel per (b,n) carrying gtm+2 (0 = not ready),
// plus consumer counters for replay-safe reset. Zero-initialized.
__device__ int g_sync[BATCH * NGT];
__device__ int g_cnt[BATCH * NGT];

// ---------------------------------------------------------------------------
// Fused kernel. grid = 8 + B*N*GXBLK = 2056 CTAs (~2 waves), 256 threads.
//   blocks 0..7    : greedy match (publishes sentinel early, volatile store)
//   blocks 8..2055 : adaptive-speculative gather (32 KB shares). Wave-2 CTAs
//                    start in known mode -> zero speculation waste; the CLC
//                    work-stealing scheduler load-balances the matched tail.
// ---------------------------------------------------------------------------
__global__ void __launch_bounds__(256, 7) fused_kernel(
                             const float* __restrict__ pred_boxes,  // [B,M,4]
                             const float* __restrict__ gt_boxes,    // [B,N,4]
                             const float* __restrict__ pred_scores, // [B,M]
                             const float* __restrict__ pred_masks,  // [B,M,H,W]
                             const float* __restrict__ mask_score,  // [B,M]
                             float* __restrict__ out)
{
    const int tid = threadIdx.x;

    if (blockIdx.x < NMATCH) {
        // =================== MATCH PATH ===================
        const int b    = blockIdx.x;
        const int wid  = tid >> 5;
        const int lane = tid & 31;      // lane = GT index

        __shared__ float4 s_pbox[MPRED];
        __shared__ float  s_score[MPRED];
        __shared__ float  s_iou[MPRED * NGT];
        __shared__ int    s_hit[128];
        __shared__ int    s_hits[MPRED];
        __shared__ int    s_sorted[MPRED];
        __shared__ int    s_nhits;

        const float4* pb4 = reinterpret_cast<const float4*>(pred_boxes + b * MPRED * 4);
        const float*  ps  = pred_scores + b * MPRED;
        if (tid < MPRED) { s_pbox[tid] = pb4[tid]; s_score[tid] = ps[tid]; }
        if (tid < 128) s_hit[tid] = 0;
        __syncthreads();

        const float* gb = gt_boxes + (b * NGT + lane) * 4;
        const float g0 = gb[0], g1 = gb[1], g2 = gb[2], g3 = gb[3];
        const float area2 = (g2 - g0) * (g3 - g1);

        // Phase A: IoU matrix + per-pred hit flags (8 warps in parallel)
        for (int p = wid; p < MPRED; p += 8) {
            const float4 pbx = s_pbox[p];
            const float area1 = (pbx.z - pbx.x) * (pbx.w - pbx.y);
            const float lx = fmaxf(pbx.x, g0), ly = fmaxf(pbx.y, g1);
            const float rx = fminf(pbx.z, g2), ry = fminf(pbx.w, g3);
            const float w  = fmaxf(rx - lx, 0.0f);
            const float h  = fmaxf(ry - ly, 0.0f);
            const float inter = w * h;
            const float iou = __fdividef(inter, area1 + area2 - inter);
            s_iou[p * NGT + lane] = iou;
            const unsigned bal = __ballot_sync(0xffffffffu, iou >= 0.5f);
            if (lane == 0) s_hit[p] = (bal != 0u) && (s_score[p] >= 0.0f);
        }
        __syncthreads();

        if (wid == 0) {
            // compaction via ballots + prefix popcount
            int nh = 0;
            #pragma unroll
            for (int k = 0; k < 4; k++) {
                const int p = k * 32 + lane;
                const int f = (p < MPRED) ? s_hit[p] : 0;
                const unsigned bal = __ballot_sync(0xffffffffu, f != 0);
                if (f) s_hits[nh + __popc(bal & ((1u << lane) - 1u))] = p;
                nh += __popc(bal);
            }
            if (lane == 0) s_nhits = nh;
            __syncwarp();
            const int K = s_nhits;

            // stable descending rank-sort (== jnp.argsort(-scores) on hit set)
            for (int t = lane; t < K; t += 32) {
                const int   hi = s_hits[t];
                const float si = s_score[hi];
                int rank = 0;
                for (int u = 0; u < K; u++) {
                    const int   hu = s_hits[u];
                    const float su = s_score[hu];
                    rank += (su > si) || (su == si && hu < hi);
                }
                s_sorted[rank] = hi;
            }
            __syncwarp();

            // serial greedy scan
            int   gtm  = -1;
            float biou = 0.0f;
            for (int t = 0; t < K; t++) {
                const int   i   = s_sorted[t];
                const float iou = s_iou[i * NGT + lane];
                // Faithful to reference: gt available iff gtm <= 0 (intentional "bug")
                const bool  valid = (gtm <= 0) && (iou >= 0.5f);
                const unsigned key  = valid ? __float_as_uint(iou) : 0u;
                const unsigned kmax = __reduce_max_sync(0xffffffffu, key);
                if (kmax != 0u) {
                    const unsigned bal = __ballot_sync(0xffffffffu, key == kmax);
                    const int m = __ffs(bal) - 1;   // lowest lane = jnp.argmax
                    if (lane == m) { gtm = i; biou = iou; }
                }
            }

            // Publish FIRST: plain volatile store (payload in flag, nonzero,
            // single word -> no fence needed, no atomic round-trip)
            const int bn = b * NGT + lane;
            *(volatile int*)&g_sync[bn] = gtm + 2;

            // Tail scalar outputs (off the critical path)
            float* flags_out = out + (long long)BATCH * NGT * HWPIX;
            float* gtm_out   = flags_out + BATCH * NGT;
            float* biou_out  = gtm_out   + BATCH * NGT;
            flags_out[bn] = (gtm > -1) ? mask_score[b * MPRED + gtm] : 0.0f;
            gtm_out[bn]   = (float)gtm;
            biou_out[bn]  = biou;
        }
    } else {
        // =================== GATHER PATH ===================
        const int u  = blockIdx.x - NMATCH;   // 0..2047
        const int bn = u >> 3;                // (b,n) id
        const int b  = bn >> 5;
        const int xq = u & 7;                 // eighth index

        __shared__ int sh_g;                  // -2 = unknown, else gtm

        volatile int* sy = (volatile int*)&g_sync[bn];

        if (tid == 0) { const int v = *sy; sh_g = v ? (v - 2) : -2; }
        __syncthreads();
        int g = sh_g;

        const int base = xq * F4_PER_BLK + tid;   // float4 units
        float4* o = reinterpret_cast<float4*>(out) + (long long)bn * F4_PER_BN + base;
        const float4 z = make_float4(0.0f, 0.0f, 0.0f, 0.0f);

        int zeroed = 0;   // chunks written speculatively as zero

        #pragma unroll
        for (int c = 0; c < NCHUNK; c++) {
            if (g >= 0) {
                // known matched: copy this chunk
                const float4* src = reinterpret_cast<const float4*>(pred_masks)
                                  + (long long)(b * MPRED + g) * F4_PER_BN + base;
                #pragma unroll
                for (int k = 0; k < IT_PER_CHUNK; k++)
                    o[(c * IT_PER_CHUNK + k) * 256] = src[(c * IT_PER_CHUNK + k) * 256];
            } else if (g == -2) {
                // unknown: issue poll load first, hide it under the zero stores
                int v = 0;
                if (tid == 0) v = *sy;
                #pragma unroll
                for (int k = 0; k < IT_PER_CHUNK; k++)
                    o[(c * IT_PER_CHUNK + k) * 256] = z;
                zeroed = c + 1;
                if (tid == 0) sh_g = v ? (v - 2) : -2;
                __syncthreads();
                g = sh_g;
            } else {
                // known unmatched: zeros are final
                #pragma unroll
                for (int k = 0; k < IT_PER_CHUNK; k++)
                    o[(c * IT_PER_CHUNK + k) * 256] = z;
            }
        }

        // Still unknown after zeroing everything: spin (thread 0 only)
        if (g == -2) {
            if (tid == 0) {
                int v = *sy;
                while (v == 0) { __nanosleep(128); v = *sy; }
                sh_g = v - 2;
            }
            __syncthreads();
            g = sh_g;
        }

        // Matched: redo the speculatively-zeroed chunks with real data.
        // (Same threads, same addresses -> program order gives final value.)
        if (g > -1) {
            const float4* src = reinterpret_cast<const float4*>(pred_masks)
                              + (long long)(b * MPRED + g) * F4_PER_BN + base;
            for (int c = 0; c < zeroed; c++) {
                #pragma unroll
                for (int k = 0; k < IT_PER_CHUNK; k++)
                    o[(c * IT_PER_CHUNK + k) * 256] = src[(c * IT_PER_CHUNK + k) * 256];
            }
        }

        // Replay-safe reset: 8th consumer CTA clears sentinel + counter.
        __syncthreads();
        if (tid == 0) {
            const int old = atomicAdd(&g_cnt[bn], 1);
            if (old == GXBLK - 1) {
                *(volatile int*)&g_cnt[bn]  = 0;
                *(volatile int*)&g_sync[bn] = 0;
            }
        }
    }
}

// ---------------------------------------------------------------------------
extern "C" void kernel_launch(void* const* d_in, const int* in_sizes, int n_in,
                              void* d_out, int out_size)
{
    const float* pred_boxes  = (const float*)d_in[0];
    const float* gt_boxes    = (const float*)d_in[1];
    const float* pred_scores = (const float*)d_in[2];
    const float* pred_masks  = (const float*)d_in[3];
    const float* mask_score  = (const float*)d_in[4];
    float* out = (float*)d_out;

    const int nblk = NMATCH + BATCH * NGT * GXBLK;   // 8 + 2048 = 2056
    fused_kernel<<<nblk, 256>>>(pred_boxes, gt_boxes, pred_scores,
                                pred_masks, mask_score, out);
}